// round 9
// baseline (speedup 1.0000x reference)
#include <cuda_runtime.h>
#include <cuda_bf16.h>

#define N_NODES 250000
#define N_EDGES 5000000
#define E8 (N_EDGES / 8)     // 625,000 threads for edge kernels
#define NN4 (N_NODES / 4)    // 62,500

// Scratch (device globals — no allocation allowed).
// g_deg is zero at process start (BSS) and re-zeroed at the end of every
// kernel_launch by k_node_c, so each call sees zeros. Deterministic.
__device__ int    g_deg[N_NODES];
__device__ float  g_dinv[N_NODES];
__device__ float  g_y[N_NODES];      // x[i] * dinv[i]
__device__ float  g_s1[N_NODES];     // layer-1 scatter accumulator
__device__ float2 g_t[N_NODES];      // per-node layer-2 message (z * dinv)
__device__ float2 g_oacc[N_NODES];   // layer-2 scatter accumulator

__device__ __forceinline__ void red_f32(float* p, float v) {
    asm volatile("red.global.add.f32 [%0], %1;" :: "l"(p), "f"(v) : "memory");
}
__device__ __forceinline__ void red_v2f32(float2* p, float2 v) {
    asm volatile("red.global.add.v2.f32 [%0], {%1, %2};"
                 :: "l"(p), "f"(v.x), "f"(v.y) : "memory");
}

// Degree pass: count in-degree from col (8 edges/thread, int32 indices)
__global__ void __launch_bounds__(256) k_edge_deg(const int* __restrict__ col) {
    int idx = blockIdx.x * blockDim.x + threadIdx.x;
    if (idx >= E8) return;
    const int4* c4 = (const int4*)col;
    int4 a = c4[2 * idx], b = c4[2 * idx + 1];
    atomicAdd(&g_deg[a.x], 1);
    atomicAdd(&g_deg[a.y], 1);
    atomicAdd(&g_deg[a.z], 1);
    atomicAdd(&g_deg[a.w], 1);
    atomicAdd(&g_deg[b.x], 1);
    atomicAdd(&g_deg[b.y], 1);
    atomicAdd(&g_deg[b.z], 1);
    atomicAdd(&g_deg[b.w], 1);
}

// Per-node (x4): dinv = rsqrt(indeg+1); y = x*dinv; s1 init with self-loop y.
__global__ void __launch_bounds__(256) k_node_a(const float* __restrict__ x) {
    int i = blockIdx.x * blockDim.x + threadIdx.x;
    if (i >= NN4) return;
    int4   d4 = ((const int4*)g_deg)[i];
    float4 x4 = ((const float4*)x)[i];
    float4 dv, y4;
    dv.x = rsqrtf((float)(d4.x + 1));
    dv.y = rsqrtf((float)(d4.y + 1));
    dv.z = rsqrtf((float)(d4.z + 1));
    dv.w = rsqrtf((float)(d4.w + 1));
    y4.x = x4.x * dv.x; y4.y = x4.y * dv.y;
    y4.z = x4.z * dv.z; y4.w = x4.w * dv.w;
    ((float4*)g_dinv)[i] = dv;
    ((float4*)g_y)[i]    = y4;
    ((float4*)g_s1)[i]   = y4;   // self-loop; final *dinv[c] in k_node_b
}

// Layer-1 scatter: s1[col] += y[row]  (8 edges/thread)
__global__ void __launch_bounds__(256) k_edge_pass2(const int* __restrict__ row,
                                                    const int* __restrict__ col) {
    int idx = blockIdx.x * blockDim.x + threadIdx.x;
    if (idx >= E8) return;
    const int4* r4 = (const int4*)row;
    const int4* c4 = (const int4*)col;
    int4 ra = r4[2 * idx], rb = r4[2 * idx + 1];
    int4 ca = c4[2 * idx], cb = c4[2 * idx + 1];
    float y0 = g_y[ra.x], y1 = g_y[ra.y], y2 = g_y[ra.z], y3 = g_y[ra.w];
    float y4 = g_y[rb.x], y5 = g_y[rb.y], y6 = g_y[rb.z], y7 = g_y[rb.w];
    red_f32(&g_s1[ca.x], y0);
    red_f32(&g_s1[ca.y], y1);
    red_f32(&g_s1[ca.z], y2);
    red_f32(&g_s1[ca.w], y3);
    red_f32(&g_s1[cb.x], y4);
    red_f32(&g_s1[cb.y], y5);
    red_f32(&g_s1[cb.z], y6);
    red_f32(&g_s1[cb.w], y7);
}

// Per-node MLP: s = dinv*s1 -> relu(W1*s+b1) @ W2 -> *dinv; init layer-2 acc.
__global__ void __launch_bounds__(256) k_node_b(const float* __restrict__ W1,
                                                const float* __restrict__ b1,
                                                const float* __restrict__ W2) {
    __shared__ float sW1[16], sB1[16], sW2[32];
    int t = threadIdx.x;
    if (t < 16) { sW1[t] = W1[t]; sB1[t] = b1[t]; }
    else if (t < 48) { sW2[t - 16] = W2[t - 16]; }
    __syncthreads();

    int i = blockIdx.x * blockDim.x + threadIdx.x;
    if (i < N_NODES) {
        float d = g_dinv[i];
        float s = d * g_s1[i];
        float z0 = 0.f, z1 = 0.f;
        #pragma unroll
        for (int j = 0; j < 16; j++) {
            float h = fmaxf(fmaf(sW1[j], s, sB1[j]), 0.f);
            z0 = fmaf(h, sW2[2 * j], z0);
            z1 = fmaf(h, sW2[2 * j + 1], z1);
        }
        z0 *= d; z1 *= d;
        g_t[i] = make_float2(z0, z1);
        g_oacc[i] = make_float2(z0, z1);  // self-loop init
    }
}

// Layer-2 scatter: oacc[col] += t[row]  (vector RED, 8 edges/thread)
__global__ void __launch_bounds__(256) k_edge_pass3(const int* __restrict__ row,
                                                    const int* __restrict__ col) {
    int idx = blockIdx.x * blockDim.x + threadIdx.x;
    if (idx >= E8) return;
    const int4* r4 = (const int4*)row;
    const int4* c4 = (const int4*)col;
    int4 ra = r4[2 * idx], rb = r4[2 * idx + 1];
    int4 ca = c4[2 * idx], cb = c4[2 * idx + 1];
    float2 t0 = g_t[ra.x], t1 = g_t[ra.y], t2 = g_t[ra.z], t3 = g_t[ra.w];
    float2 t4 = g_t[rb.x], t5 = g_t[rb.y], t6 = g_t[rb.z], t7 = g_t[rb.w];
    red_v2f32(&g_oacc[ca.x], t0);
    red_v2f32(&g_oacc[ca.y], t1);
    red_v2f32(&g_oacc[ca.z], t2);
    red_v2f32(&g_oacc[ca.w], t3);
    red_v2f32(&g_oacc[cb.x], t4);
    red_v2f32(&g_oacc[cb.y], t5);
    red_v2f32(&g_oacc[cb.z], t6);
    red_v2f32(&g_oacc[cb.w], t7);
}

// Final: scale by dinv, add b2, 2-way softmax (2 nodes/thread via float4).
// Also re-zeroes g_deg for the next call (deterministic across replays).
__global__ void __launch_bounds__(256) k_node_c(const float* __restrict__ b2,
                                                float* __restrict__ out) {
    int i = blockIdx.x * blockDim.x + threadIdx.x;   // pair index
    if (i >= N_NODES / 2) return;
    float bb0 = b2[0], bb1 = b2[1];
    float2 dv = ((const float2*)g_dinv)[i];
    float4 a  = ((const float4*)g_oacc)[i];   // two float2 accumulators
    float4 o;
    {
        float o0 = fmaf(dv.x, a.x, bb0);
        float o1 = fmaf(dv.x, a.y, bb1);
        float m = fmaxf(o0, o1);
        float e0 = __expf(o0 - m), e1 = __expf(o1 - m);
        float inv = __frcp_rn(e0 + e1);
        o.x = e0 * inv; o.y = e1 * inv;
    }
    {
        float o0 = fmaf(dv.y, a.z, bb0);
        float o1 = fmaf(dv.y, a.w, bb1);
        float m = fmaxf(o0, o1);
        float e0 = __expf(o0 - m), e1 = __expf(o1 - m);
        float inv = __frcp_rn(e0 + e1);
        o.z = e0 * inv; o.w = e1 * inv;
    }
    ((float4*)out)[i] = o;
    ((int2*)g_deg)[i] = make_int2(0, 0);   // zero for next call
}

extern "C" void kernel_launch(void* const* d_in, const int* in_sizes, int n_in,
                              void* d_out, int out_size) {
    const float* x   = (const float*)d_in[0];
    const int*   row = (const int*)d_in[1];            // [2, N_EDGES] int32
    const int*   col = row + N_EDGES;
    const float* W1  = (const float*)d_in[2];
    const float* b1  = (const float*)d_in[3];
    const float* W2  = (const float*)d_in[4];
    const float* b2  = (const float*)d_in[5];
    float* out = (float*)d_out;

    const int BT = 256;
    const int nodeGrid  = (N_NODES + BT - 1) / BT;
    const int node4Grid = (NN4 + BT - 1) / BT;
    const int pairGrid  = (N_NODES / 2 + BT - 1) / BT;
    const int edge8Grid = (E8 + BT - 1) / BT;

    k_edge_deg<<<edge8Grid, BT>>>(col);
    k_node_a<<<node4Grid, BT>>>(x);
    k_edge_pass2<<<edge8Grid, BT>>>(row, col);
    k_node_b<<<nodeGrid, BT>>>(W1, b1, W2);
    k_edge_pass3<<<edge8Grid, BT>>>(row, col);
    k_node_c<<<pairGrid, BT>>>(b2, out);
}